// round 5
// baseline (speedup 1.0000x reference)
#include <cuda_runtime.h>
#include <math.h>

#define B    4
#define C    64
#define H    128
#define W    128
#define COUT 64
#define KK   18       // 2*K offset channels
#define CK   576      // C*9
#define HW   16384    // H*W
#define TPX  64       // pixels per main-kernel block
#define NT   256      // threads in k_main
#define SROW 68       // padded samp row (64 + 4)

// Scratch (device globals — no runtime allocation allowed)
__device__ float g_xt[B * HW * C];       // x transposed to [b][y][x][c]
__device__ float g_off[B * HW * KK];     // offsets [b][y][x][18]
__device__ float g_wkt2[9 * C * COUT];   // weights [k][c][o]

__device__ __forceinline__ void fma4(float4& a, float s, const float4& v) {
    a.x += s * v.x; a.y += s * v.y; a.z += s * v.z; a.w += s * v.w;
}

// ---------------------------------------------------------------------------
// Kernel 1: transpose x (B,C,H,W) -> (B,HW,C), SMEM-tiled 32x32
// ---------------------------------------------------------------------------
__global__ void k_transpose_x(const float* __restrict__ x) {
    __shared__ float tile[32][33];
    int b   = blockIdx.z;
    int c0  = blockIdx.y * 32;
    int hw0 = blockIdx.x * 32;
    int tx = threadIdx.x, ty = threadIdx.y;   // 32 x 8
#pragma unroll
    for (int j = 0; j < 4; j++) {
        int c = c0 + ty + j * 8;
        tile[ty + j * 8][tx] = x[(b * C + c) * HW + hw0 + tx];
    }
    __syncthreads();
#pragma unroll
    for (int j = 0; j < 4; j++) {
        int hw = hw0 + ty + j * 8;
        g_xt[(b * HW + hw) * C + c0 + tx] = tile[tx][ty + j * 8];
    }
}

// ---------------------------------------------------------------------------
// Kernel 2: reorder w_d (COUT, C, 3, 3) -> g_wkt2[k][c][o]
// ---------------------------------------------------------------------------
__global__ void k_wkt(const float* __restrict__ wd) {
    int d = blockIdx.x * 256 + threadIdx.x;
    if (d < 9 * C * COUT) {
        int o = d & 63;
        int c = (d >> 6) & 63;
        int k = d >> 12;
        g_wkt2[d] = wd[o * CK + c * 9 + k];
    }
}

// ---------------------------------------------------------------------------
// Kernel 3: offset conv — 3x3, C=64 -> 18, pad 1, + bias.
// ---------------------------------------------------------------------------
__global__ void __launch_bounds__(256) k_offset(const float* __restrict__ x,
                                                const float* __restrict__ wp,
                                                const float* __restrict__ bp) {
    __shared__ float ws[C * 9 * 20];   // 46080 B
    int tid = threadIdx.x;
    for (int i = tid; i < C * 9 * 20; i += 256) {
        int kk = i % 20;
        int ct = i / 20;               // c*9 + tap
        ws[i] = (kk < 18) ? wp[kk * CK + ct] : 0.f;
    }
    __syncthreads();

    int pid = blockIdx.x * 256 + tid;
    int b  = pid >> 14;
    int yx = pid & (HW - 1);
    int y  = yx >> 7;
    int xx = yx & 127;

    float4 acc[5];
    {
        float a[20];
#pragma unroll
        for (int kk = 0; kk < 18; kk++) a[kk] = bp[kk];
        a[18] = 0.f; a[19] = 0.f;
#pragma unroll
        for (int q = 0; q < 5; q++)
            acc[q] = make_float4(a[4*q], a[4*q+1], a[4*q+2], a[4*q+3]);
    }

    const float* xb = x + b * C * HW;
    for (int c = 0; c < C; c++) {
        float v[9];
#pragma unroll
        for (int t = 0; t < 9; t++) {
            int yy = y + t / 3 - 1;
            int xc = xx + t % 3 - 1;
            bool ok = (yy >= 0 && yy < H && xc >= 0 && xc < W);
            v[t] = ok ? xb[c * HW + yy * W + xc] : 0.f;
        }
#pragma unroll
        for (int t = 0; t < 9; t++) {
            const float4* w4 = (const float4*)&ws[(c * 9 + t) * 20];
            float vv = v[t];
#pragma unroll
            for (int q = 0; q < 5; q++) {
                float4 wq = w4[q];
                acc[q].x += vv * wq.x;
                acc[q].y += vv * wq.y;
                acc[q].z += vv * wq.z;
                acc[q].w += vv * wq.w;
            }
        }
    }

    float a[20];
#pragma unroll
    for (int q = 0; q < 5; q++) {
        a[4*q] = acc[q].x; a[4*q+1] = acc[q].y;
        a[4*q+2] = acc[q].z; a[4*q+3] = acc[q].w;
    }
    float* op = g_off + (long)pid * KK;
#pragma unroll
    for (int kk = 0; kk < 18; kk++) op[kk] = a[kk];
}

// ---------------------------------------------------------------------------
// Kernel 4: main. 256 threads, 64 pixels (half a row) per block.
// Per-tap fused pipeline with double-buffered samp tile:
//   for k in 0..8:  sample tap k -> samp[k&1]; sync; GEMM-accumulate tap k
// Weights read directly from global (broadcast, L1-cached).
// Dynamic smem: 2 * 64px * SROW(68) * 4B = 34816 B -> high occupancy.
// ---------------------------------------------------------------------------
__global__ void __launch_bounds__(NT) k_main(float* __restrict__ out) {
    extern __shared__ float smem[];    // samp[2][TPX][SROW]

    int b   = blockIdx.z;
    int y   = blockIdx.y;
    int x0  = blockIdx.x * TPX;
    int tid = threadIdx.x;

    // sampling identity: thread -> (pixel t, 16 channels)
    int st  = tid >> 2;              // 0..63
    int sc0 = (tid & 3) * 16;        // 0,16,32,48
    int sxo = x0 + st;
    const float* op = g_off + (long)(b * HW + y * W + sxo) * KK;
    float* srowb = smem + st * SROW + sc0;

    // GEMM identity: thread -> 4 outputs (o0..o0+3) x 4 pixels (t0..t0+3)
    int o0 = (tid & 15) * 4;
    int t0 = (tid >> 4) * 4;         // 0,4,...,60
    float4 acc[4];
#pragma unroll
    for (int i = 0; i < 4; i++) acc[i] = make_float4(0, 0, 0, 0);

#pragma unroll
    for (int k = 0; k < 9; k++) {
        // ---- sample tap k into buffer (k & 1)
        {
            int ky = k / 3, kx = k % 3;
            float py = op[2*k]     + (float)(y   + ky - 1);
            float px = op[2*k + 1] + (float)(sxo + kx - 1);
            float fy = floorf(py), fx = floorf(px);
            float wy = py - fy,    wx = px - fx;
            int iy0 = (int)fy, ix0 = (int)fx;
            int iy1 = iy0 + 1, ix1 = ix0 + 1;
            float vy0 = (iy0 >= 0 && iy0 < H) ? 1.f : 0.f;
            float vy1 = (iy1 >= 0 && iy1 < H) ? 1.f : 0.f;
            float vx0 = (ix0 >= 0 && ix0 < W) ? 1.f : 0.f;
            float vx1 = (ix1 >= 0 && ix1 < W) ? 1.f : 0.f;
            float w00 = (1.f - wy) * (1.f - wx) * vy0 * vx0;
            float w01 = (1.f - wy) * wx         * vy0 * vx1;
            float w10 = wy         * (1.f - wx) * vy1 * vx0;
            float w11 = wy         * wx         * vy1 * vx1;
            int cy0 = min(max(iy0, 0), H - 1), cy1 = min(max(iy1, 0), H - 1);
            int cx0 = min(max(ix0, 0), W - 1), cx1 = min(max(ix1, 0), W - 1);
            const float* p00 = g_xt + ((long)(b * HW + cy0 * W + cx0)) * C + sc0;
            const float* p01 = g_xt + ((long)(b * HW + cy0 * W + cx1)) * C + sc0;
            const float* p10 = g_xt + ((long)(b * HW + cy1 * W + cx0)) * C + sc0;
            const float* p11 = g_xt + ((long)(b * HW + cy1 * W + cx1)) * C + sc0;
            float* dst = srowb + (k & 1) * (TPX * SROW);
#pragma unroll
            for (int j = 0; j < 4; j++) {
                float4 a00 = *(const float4*)(p00 + 4*j);
                float4 a01 = *(const float4*)(p01 + 4*j);
                float4 a10 = *(const float4*)(p10 + 4*j);
                float4 a11 = *(const float4*)(p11 + 4*j);
                float s0 = w00*a00.x + w01*a01.x + w10*a10.x + w11*a11.x;
                float s1 = w00*a00.y + w01*a01.y + w10*a10.y + w11*a11.y;
                float s2 = w00*a00.z + w01*a01.z + w10*a10.z + w11*a11.z;
                float s3 = w00*a00.w + w01*a01.w + w10*a10.w + w11*a11.w;
                *(float4*)(dst + 4*j) = make_float4(s0, s1, s2, s3);
            }
        }
        __syncthreads();

        // ---- GEMM-accumulate tap k
        {
            const float* sp = smem + (k & 1) * (TPX * SROW) + t0 * SROW;
            const float* wk = g_wkt2 + k * (C * COUT);
#pragma unroll 4
            for (int cq = 0; cq < 16; cq++) {
                int c = cq * 4;
                float4 sa = *(const float4*)(sp + 0 * SROW + c);
                float4 sb = *(const float4*)(sp + 1 * SROW + c);
                float4 sc = *(const float4*)(sp + 2 * SROW + c);
                float4 sd = *(const float4*)(sp + 3 * SROW + c);
                float4 w0 = *(const float4*)(wk + (c + 0) * COUT + o0);
                float4 w1 = *(const float4*)(wk + (c + 1) * COUT + o0);
                float4 w2 = *(const float4*)(wk + (c + 2) * COUT + o0);
                float4 w3 = *(const float4*)(wk + (c + 3) * COUT + o0);
                fma4(acc[0], sa.x, w0); fma4(acc[0], sa.y, w1);
                fma4(acc[0], sa.z, w2); fma4(acc[0], sa.w, w3);
                fma4(acc[1], sb.x, w0); fma4(acc[1], sb.y, w1);
                fma4(acc[1], sb.z, w2); fma4(acc[1], sb.w, w3);
                fma4(acc[2], sc.x, w0); fma4(acc[2], sc.y, w1);
                fma4(acc[2], sc.z, w2); fma4(acc[2], sc.w, w3);
                fma4(acc[3], sd.x, w0); fma4(acc[3], sd.y, w1);
                fma4(acc[3], sd.z, w2); fma4(acc[3], sd.w, w3);
            }
        }
        // No sync needed here: next tap samples into the OTHER buffer, and the
        // sync after that sampling orders it before anyone overwrites this one.
    }

    // ---- Output: stage through SMEM (reuse buffer 0) for coalesced stores
    __syncthreads();
    float* ob = smem;                 // [COUT][SROW]
#pragma unroll
    for (int i = 0; i < 4; i++)
#pragma unroll
        for (int j = 0; j < 4; j++)
            ob[(o0 + i) * SROW + t0 + j] = (&acc[j].x)[i];
    __syncthreads();
#pragma unroll
    for (int j = 0; j < 16; j++) {
        int i = tid + j * NT;
        int o = i >> 6;
        int t = i & 63;
        out[((long)(b * COUT + o) * H + y) * W + x0 + t] = ob[o * SROW + t];
    }
}

// ---------------------------------------------------------------------------
extern "C" void kernel_launch(void* const* d_in, const int* in_sizes, int n_in,
                              void* d_out, int out_size) {
    const float* x  = (const float*)d_in[0];
    const float* wp = (const float*)d_in[1];
    const float* bp = (const float*)d_in[2];
    const float* wd = (const float*)d_in[3];
    float* out = (float*)d_out;

    static int smem_set = 0;
    int smem_bytes = 2 * TPX * SROW * 4;   // 34816
    if (!smem_set) {
        cudaFuncSetAttribute(k_main, cudaFuncAttributeMaxDynamicSharedMemorySize,
                             smem_bytes);
        smem_set = 1;
    }

    k_transpose_x<<<dim3(HW / 32, C / 32, B), dim3(32, 8)>>>(x);
    k_wkt<<<(9 * C * COUT + 255) / 256, 256>>>(wd);
    k_offset<<<(B * HW) / 256, 256>>>(x, wp, bp);
    k_main<<<dim3(W / TPX, H, B), NT, smem_bytes>>>(out);
}

// round 7
// speedup vs baseline: 1.1758x; 1.1758x over previous
#include <cuda_runtime.h>
#include <cuda_bf16.h>
#include <math.h>
#include <stdint.h>

#define B    4
#define C    64
#define H    128
#define W    128
#define COUT 64
#define KK   18
#define CK   576
#define HW   16384
#define NTILES 512            // 65536 px / 128; one tile = one image row
#define RPAD 144              // smem row pitch in bytes (72 bf16)

// Scratch (device globals — no runtime allocation allowed)
__device__ float g_xt[B * HW * C];           // x transposed to [b][y][x][c]
__device__ float g_off[B * HW * KK];         // offsets [b][y][x][18]
__device__ __nv_bfloat16 g_Bhi[9 * 64 * 64]; // weights [tap][o][c] bf16 hi
__device__ __nv_bfloat16 g_Blo[9 * 64 * 64]; // weights [tap][o][c] bf16 lo

// ---------------- warp-MMA helpers (baseline PTX, sm_80+) ----------------
__device__ __forceinline__ uint32_t smem_u32(const void* p) {
    uint32_t a;
    asm("{ .reg .u64 t; cvta.to.shared.u64 t, %1; cvt.u32.u64 %0, t; }"
        : "=r"(a) : "l"(p));
    return a;
}
__device__ __forceinline__ void ldsm_x4(uint32_t* r, uint32_t addr) {
    asm volatile("ldmatrix.sync.aligned.m8n8.x4.shared.b16 {%0,%1,%2,%3}, [%4];"
                 : "=r"(r[0]), "=r"(r[1]), "=r"(r[2]), "=r"(r[3]) : "r"(addr));
}
__device__ __forceinline__ void ldsm_x2(uint32_t* r, uint32_t addr) {
    asm volatile("ldmatrix.sync.aligned.m8n8.x2.shared.b16 {%0,%1}, [%2];"
                 : "=r"(r[0]), "=r"(r[1]) : "r"(addr));
}
__device__ __forceinline__ void mma_bf16(float* c, const uint32_t* a,
                                         const uint32_t* b) {
    asm volatile(
        "mma.sync.aligned.m16n8k16.row.col.f32.bf16.bf16.f32 "
        "{%0,%1,%2,%3}, {%4,%5,%6,%7}, {%8,%9}, {%0,%1,%2,%3};"
        : "+f"(c[0]), "+f"(c[1]), "+f"(c[2]), "+f"(c[3])
        : "r"(a[0]), "r"(a[1]), "r"(a[2]), "r"(a[3]), "r"(b[0]), "r"(b[1]));
}
__device__ __forceinline__ unsigned bpack(float a, float b) {
    __nv_bfloat162 t;
    t.x = __float2bfloat16(a); t.y = __float2bfloat16(b);
    return *reinterpret_cast<unsigned*>(&t);
}

// ---------------------------------------------------------------------------
// Kernel 1: transpose x (B,C,H,W) -> (B,HW,C)
// ---------------------------------------------------------------------------
__global__ void k_transpose_x(const float* __restrict__ x) {
    __shared__ float tile[32][33];
    int b   = blockIdx.z;
    int c0  = blockIdx.y * 32;
    int hw0 = blockIdx.x * 32;
    int tx = threadIdx.x, ty = threadIdx.y;
#pragma unroll
    for (int j = 0; j < 4; j++)
        tile[ty + j * 8][tx] = x[(b * C + c0 + ty + j * 8) * HW + hw0 + tx];
    __syncthreads();
#pragma unroll
    for (int j = 0; j < 4; j++)
        g_xt[(b * HW + hw0 + ty + j * 8) * C + c0 + tx] = tile[tx][ty + j * 8];
}

// ---------------------------------------------------------------------------
// Kernel 2: weight prep — bf16 hi/lo split to [tap][o][c]
// ---------------------------------------------------------------------------
__global__ void k_wprep(const float* __restrict__ wd) {
    int i = blockIdx.x * 256 + threadIdx.x;
    if (i >= 9 * 64 * 64) return;
    int c = i & 63, o = (i >> 6) & 63, k = i >> 12;
    float v = wd[o * CK + c * 9 + k];
    __nv_bfloat16 h = __float2bfloat16(v);
    g_Bhi[k * 4096 + o * 64 + c] = h;
    g_Blo[k * 4096 + o * 64 + c] = __float2bfloat16(v - __bfloat162float(h));
}

// ---------------------------------------------------------------------------
// Kernel 3: offset conv — 3x3, C=64 -> 18, pad 1, + bias.
// ---------------------------------------------------------------------------
__global__ void __launch_bounds__(256) k_offset(const float* __restrict__ x,
                                                const float* __restrict__ wp,
                                                const float* __restrict__ bp) {
    __shared__ float ws[C * 9 * 20];
    int tid = threadIdx.x;
    for (int i = tid; i < C * 9 * 20; i += 256) {
        int kk = i % 20;
        int ct = i / 20;
        ws[i] = (kk < 18) ? wp[kk * CK + ct] : 0.f;
    }
    __syncthreads();

    int pid = blockIdx.x * 256 + tid;
    int b  = pid >> 14;
    int yx = pid & (HW - 1);
    int y  = yx >> 7;
    int xx = yx & 127;

    float4 acc[5];
    {
        float a[20];
#pragma unroll
        for (int kk = 0; kk < 18; kk++) a[kk] = bp[kk];
        a[18] = 0.f; a[19] = 0.f;
#pragma unroll
        for (int q = 0; q < 5; q++)
            acc[q] = make_float4(a[4*q], a[4*q+1], a[4*q+2], a[4*q+3]);
    }

    const float* xb = x + b * C * HW;
    for (int c = 0; c < C; c++) {
        float v[9];
#pragma unroll
        for (int t = 0; t < 9; t++) {
            int yy = y + t / 3 - 1;
            int xc = xx + t % 3 - 1;
            bool ok = (yy >= 0 && yy < H && xc >= 0 && xc < W);
            v[t] = ok ? xb[c * HW + yy * W + xc] : 0.f;
        }
#pragma unroll
        for (int t = 0; t < 9; t++) {
            const float4* w4 = (const float4*)&ws[(c * 9 + t) * 20];
            float vv = v[t];
#pragma unroll
            for (int q = 0; q < 5; q++) {
                float4 wq = w4[q];
                acc[q].x += vv * wq.x;
                acc[q].y += vv * wq.y;
                acc[q].z += vv * wq.z;
                acc[q].w += vv * wq.w;
            }
        }
    }

    float a[20];
#pragma unroll
    for (int q = 0; q < 5; q++) {
        a[4*q] = acc[q].x; a[4*q+1] = acc[q].y;
        a[4*q+2] = acc[q].z; a[4*q+3] = acc[q].w;
    }
    float* op = g_off + (long)pid * KK;
#pragma unroll
    for (int kk = 0; kk < 18; kk++) op[kk] = a[kk];
}

// ---------------------------------------------------------------------------
// Kernel 4: fused gather + bf16-split warp-MMA GEMM.
// One block = 128 px (one image row) x 64 outputs, 256 threads (8 warps).
// Per tap k: gather 128px x 64ch -> smem A_hi/A_lo [128][72] bf16;
//            load weights tap k -> smem B_hi/B_lo [64][72] bf16;
//            8 warps: 3 split passes x 4 k16-steps x (2m x 4n) mma.
// SMEM: 2*18432 (A) + 2*9216 (B) = 55296 B. Epilogue stages C via smem.
// ---------------------------------------------------------------------------
__global__ void __launch_bounds__(256, 2) k_fused(float* __restrict__ out) {
    extern __shared__ char smem[];
    char* sAhi = smem;
    char* sAlo = smem + 18432;
    char* sBhi = smem + 36864;
    char* sBlo = smem + 46080;
    uint32_t sb  = smem_u32(smem);
    uint32_t AHI = sb, ALO = sb + 18432, BHI = sb + 36864, BLO = sb + 46080;

    int tid  = threadIdx.x;
    int lane = tid & 31;
    int wid  = tid >> 5;
    int tile = blockIdx.x;
    int b    = tile >> 7;          // tile = b*128 + y
    int y    = tile & 127;

    // sampler identity: thread -> (pixel px, 32 channels at c0)
    int px = tid & 127;
    int c0 = (tid >> 7) * 32;
    const float* op = g_off + (long)(b * HW + y * W + px) * KK;

    // mma identity: warp -> m = (wid&3)*32, n = (wid>>2)*32
    int wm = (wid & 3) * 32;
    int wn = (wid >> 2) * 32;
    float acc[2][4][4];
#pragma unroll
    for (int i = 0; i < 2; i++)
#pragma unroll
        for (int j = 0; j < 4; j++)
#pragma unroll
            for (int q = 0; q < 4; q++) acc[i][j][q] = 0.f;

    // ldmatrix source addresses (constant across taps/passes except base+kcol)
    uint32_t a_row = (uint32_t)(px & 15);          // reuse px var? compute per-use
    (void)a_row;

#pragma unroll 1
    for (int k = 0; k < 9; k++) {
        // ---- gather tap k -> A_hi/A_lo
        {
            int ky = k / 3, kx = k % 3;
            float py  = op[2*k]     + (float)(y  + ky - 1);
            float pxx = op[2*k + 1] + (float)(px + kx - 1);
            float fy = floorf(py), fx = floorf(pxx);
            float wy = py - fy,    wx = pxx - fx;
            int iy0 = (int)fy, ix0 = (int)fx;
            int iy1 = iy0 + 1, ix1 = ix0 + 1;
            float vy0 = (iy0 >= 0 && iy0 < H) ? 1.f : 0.f;
            float vy1 = (iy1 >= 0 && iy1 < H) ? 1.f : 0.f;
            float vx0 = (ix0 >= 0 && ix0 < W) ? 1.f : 0.f;
            float vx1 = (ix1 >= 0 && ix1 < W) ? 1.f : 0.f;
            float w00 = (1.f - wy) * (1.f - wx) * vy0 * vx0;
            float w01 = (1.f - wy) * wx         * vy0 * vx1;
            float w10 = wy         * (1.f - wx) * vy1 * vx0;
            float w11 = wy         * wx         * vy1 * vx1;
            int cy0 = min(max(iy0, 0), H - 1), cy1 = min(max(iy1, 0), H - 1);
            int cx0 = min(max(ix0, 0), W - 1), cx1 = min(max(ix1, 0), W - 1);
            const float* p00 = g_xt + ((long)(b * HW + cy0 * W + cx0)) * C + c0;
            const float* p01 = g_xt + ((long)(b * HW + cy0 * W + cx1)) * C + c0;
            const float* p10 = g_xt + ((long)(b * HW + cy1 * W + cx0)) * C + c0;
            const float* p11 = g_xt + ((long)(b * HW + cy1 * W + cx1)) * C + c0;
            char* rh = sAhi + px * RPAD + c0 * 2;
            char* rl = sAlo + px * RPAD + c0 * 2;
#pragma unroll
            for (int j = 0; j < 8; j++) {
                float4 a00 = *(const float4*)(p00 + 4*j);
                float4 a01 = *(const float4*)(p01 + 4*j);
                float4 a10 = *(const float4*)(p10 + 4*j);
                float4 a11 = *(const float4*)(p11 + 4*j);
                float s0 = w00*a00.x + w01*a01.x + w10*a10.x + w11*a11.x;
                float s1 = w00*a00.y + w01*a01.y + w10*a10.y + w11*a11.y;
                float s2 = w00*a00.z + w01*a01.z + w10*a10.z + w11*a11.z;
                float s3 = w00*a00.w + w01*a01.w + w10*a10.w + w11*a11.w;
                unsigned h0 = bpack(s0, s1), h1 = bpack(s2, s3);
                float r0 = s0 - __bfloat162float(__float2bfloat16(s0));
                float r1 = s1 - __bfloat162float(__float2bfloat16(s1));
                float r2 = s2 - __bfloat162float(__float2bfloat16(s2));
                float r3 = s3 - __bfloat162float(__float2bfloat16(s3));
                *(uint2*)(rh + 8*j) = make_uint2(h0, h1);
                *(uint2*)(rl + 8*j) = make_uint2(bpack(r0, r1), bpack(r2, r3));
            }
        }
        // ---- load weights tap k -> B_hi/B_lo (padded rows)
        {
            const uint4* bh = (const uint4*)(g_Bhi + k * 4096);
            const uint4* bl = (const uint4*)(g_Blo + k * 4096);
#pragma unroll
            for (int j = 0; j < 2; j++) {
                int idx = tid + j * 256;         // 512 x 16B chunks
                int o   = idx >> 3;
                int kc  = idx & 7;
                *(uint4*)(sBhi + o * RPAD + kc * 16) = bh[idx];
                *(uint4*)(sBlo + o * RPAD + kc * 16) = bl[idx];
            }
        }
        __syncthreads();

        // ---- MMA: 3 passes (hi*hi, hi*lo, lo*hi) x 4 k-steps
#pragma unroll
        for (int p3 = 0; p3 < 3; p3++) {
            uint32_t Ab = (p3 == 2) ? ALO : AHI;
            uint32_t Bb = (p3 == 1) ? BLO : BHI;
#pragma unroll
            for (int ks = 0; ks < 4; ks++) {
                int kcol = ks * 16;
                uint32_t af[2][4], bfr[4][2];
#pragma unroll
                for (int mf = 0; mf < 2; mf++) {
                    uint32_t addr = Ab
                        + (uint32_t)(wm + mf * 16 + (lane & 15)) * RPAD
                        + (uint32_t)(kcol + (lane >> 4) * 8) * 2;
                    ldsm_x4(af[mf], addr);
                }
#pragma unroll
                for (int nf = 0; nf < 4; nf++) {
                    uint32_t addr = Bb
                        + (uint32_t)(wn + nf * 8 + (lane & 7)) * RPAD
                        + (uint32_t)(kcol + ((lane >> 3) & 1) * 8) * 2;
                    ldsm_x2(bfr[nf], addr);
                }
#pragma unroll
                for (int mf = 0; mf < 2; mf++)
#pragma unroll
                    for (int nf = 0; nf < 4; nf++)
                        mma_bf16(acc[mf][nf], af[mf], bfr[nf]);
            }
        }
        __syncthreads();   // done reading A/B before next tap overwrites
    }

    // ---- epilogue: transpose C through smem, store coalesced NCHW rows
    float* Cst = (float*)smem;     // [64 o][132 px]
#pragma unroll
    for (int mf = 0; mf < 2; mf++)
#pragma unroll
        for (int nf = 0; nf < 4; nf++) {
            int row0 = wm + mf * 16 + (lane >> 2);
            int col0 = wn + nf * 8 + (lane & 3) * 2;
            Cst[(col0    ) * 132 + row0    ] = acc[mf][nf][0];
            Cst[(col0 + 1) * 132 + row0    ] = acc[mf][nf][1];
            Cst[(col0    ) * 132 + row0 + 8] = acc[mf][nf][2];
            Cst[(col0 + 1) * 132 + row0 + 8] = acc[mf][nf][3];
        }
    __syncthreads();
    float* ob = out + ((long)b * COUT) * HW + y * W;
#pragma unroll
    for (int j = 0; j < 8; j++) {
        int idx = tid + j * 256;       // 2048 float4 chunks
        int o   = idx >> 5;
        int p4  = (idx & 31) * 4;
        float4 v = *(const float4*)(Cst + o * 132 + p4);
        *(float4*)(ob + (long)o * HW + p4) = v;
    }
}

// ---------------------------------------------------------------------------
extern "C" void kernel_launch(void* const* d_in, const int* in_sizes, int n_in,
                              void* d_out, int out_size) {
    const float* x  = (const float*)d_in[0];
    const float* wp = (const float*)d_in[1];
    const float* bp = (const float*)d_in[2];
    const float* wd = (const float*)d_in[3];
    float* out = (float*)d_out;

    static int smem_set = 0;
    int fused_smem = 55296;
    if (!smem_set) {
        cudaFuncSetAttribute(k_fused, cudaFuncAttributeMaxDynamicSharedMemorySize,
                             fused_smem);
        smem_set = 1;
    }

    k_transpose_x<<<dim3(HW / 32, C / 32, B), dim3(32, 8)>>>(x);
    k_wprep<<<(9 * 64 * 64 + 255) / 256, 256>>>(wd);
    k_offset<<<(B * HW) / 256, 256>>>(x, wp, bp);
    k_fused<<<NTILES, 256, fused_smem>>>(out);
}

// round 8
// speedup vs baseline: 2.0693x; 1.7599x over previous
#include <cuda_runtime.h>
#include <cuda_bf16.h>
#include <math.h>
#include <stdint.h>

#define B    4
#define C    64
#define H    128
#define W    128
#define COUT 64
#define KK   18
#define CK   576
#define HW   16384
#define NTILES 512            // 65536 px / 128; one tile = one image row
#define RPAD 144              // smem row pitch in bytes (72 bf16)

// Scratch (device globals — no runtime allocation allowed)
__device__ float g_xt[B * HW * C];           // x transposed to [b][y][x][c]
__device__ float g_off[B * HW * KK];         // offsets [b][y][x][18]
__device__ __nv_bfloat16 g_Bhi[9 * 64 * 64]; // weights [tap][o][c] bf16 hi
__device__ __nv_bfloat16 g_Blo[9 * 64 * 64]; // weights [tap][o][c] bf16 lo

// ---------------- warp-MMA helpers (baseline PTX, sm_80+) ----------------
__device__ __forceinline__ uint32_t smem_u32(const void* p) {
    uint32_t a;
    asm("{ .reg .u64 t; cvta.to.shared.u64 t, %1; cvt.u32.u64 %0, t; }"
        : "=r"(a) : "l"(p));
    return a;
}
__device__ __forceinline__ void ldsm_x4(uint32_t* r, uint32_t addr) {
    asm volatile("ldmatrix.sync.aligned.m8n8.x4.shared.b16 {%0,%1,%2,%3}, [%4];"
                 : "=r"(r[0]), "=r"(r[1]), "=r"(r[2]), "=r"(r[3]) : "r"(addr));
}
__device__ __forceinline__ void ldsm_x2(uint32_t* r, uint32_t addr) {
    asm volatile("ldmatrix.sync.aligned.m8n8.x2.shared.b16 {%0,%1}, [%2];"
                 : "=r"(r[0]), "=r"(r[1]) : "r"(addr));
}
__device__ __forceinline__ void mma_bf16(float* c, const uint32_t* a,
                                         const uint32_t* b) {
    asm volatile(
        "mma.sync.aligned.m16n8k16.row.col.f32.bf16.bf16.f32 "
        "{%0,%1,%2,%3}, {%4,%5,%6,%7}, {%8,%9}, {%0,%1,%2,%3};"
        : "+f"(c[0]), "+f"(c[1]), "+f"(c[2]), "+f"(c[3])
        : "r"(a[0]), "r"(a[1]), "r"(a[2]), "r"(a[3]), "r"(b[0]), "r"(b[1]));
}
__device__ __forceinline__ unsigned bpack(float a, float b) {
    __nv_bfloat162 t;
    t.x = __float2bfloat16(a); t.y = __float2bfloat16(b);
    return *reinterpret_cast<unsigned*>(&t);
}

// ---------------------------------------------------------------------------
// Kernel 1: transpose x (B,C,H,W) -> (B,HW,C)
// ---------------------------------------------------------------------------
__global__ void k_transpose_x(const float* __restrict__ x) {
    __shared__ float tile[32][33];
    int b   = blockIdx.z;
    int c0  = blockIdx.y * 32;
    int hw0 = blockIdx.x * 32;
    int tx = threadIdx.x, ty = threadIdx.y;
#pragma unroll
    for (int j = 0; j < 4; j++)
        tile[ty + j * 8][tx] = x[(b * C + c0 + ty + j * 8) * HW + hw0 + tx];
    __syncthreads();
#pragma unroll
    for (int j = 0; j < 4; j++)
        g_xt[(b * HW + hw0 + ty + j * 8) * C + c0 + tx] = tile[tx][ty + j * 8];
}

// ---------------------------------------------------------------------------
// Kernel 2: weight prep — bf16 hi/lo split to [tap][o][c]
// ---------------------------------------------------------------------------
__global__ void k_wprep(const float* __restrict__ wd) {
    int i = blockIdx.x * 256 + threadIdx.x;
    if (i >= 9 * 64 * 64) return;
    int c = i & 63, o = (i >> 6) & 63, k = i >> 12;
    float v = wd[o * CK + c * 9 + k];
    __nv_bfloat16 h = __float2bfloat16(v);
    g_Bhi[k * 4096 + o * 64 + c] = h;
    g_Blo[k * 4096 + o * 64 + c] = __float2bfloat16(v - __bfloat162float(h));
}

// ---------------------------------------------------------------------------
// Kernel 3: offset conv — 3x3, C=64 -> 18, pad 1, + bias.
// ---------------------------------------------------------------------------
__global__ void __launch_bounds__(256) k_offset(const float* __restrict__ x,
                                                const float* __restrict__ wp,
                                                const float* __restrict__ bp) {
    __shared__ float ws[C * 9 * 20];
    int tid = threadIdx.x;
    for (int i = tid; i < C * 9 * 20; i += 256) {
        int kk = i % 20;
        int ct = i / 20;
        ws[i] = (kk < 18) ? wp[kk * CK + ct] : 0.f;
    }
    __syncthreads();

    int pid = blockIdx.x * 256 + tid;
    int b  = pid >> 14;
    int yx = pid & (HW - 1);
    int y  = yx >> 7;
    int xx = yx & 127;

    float4 acc[5];
    {
        float a[20];
#pragma unroll
        for (int kk = 0; kk < 18; kk++) a[kk] = bp[kk];
        a[18] = 0.f; a[19] = 0.f;
#pragma unroll
        for (int q = 0; q < 5; q++)
            acc[q] = make_float4(a[4*q], a[4*q+1], a[4*q+2], a[4*q+3]);
    }

    const float* xb = x + b * C * HW;
    for (int c = 0; c < C; c++) {
        float v[9];
#pragma unroll
        for (int t = 0; t < 9; t++) {
            int yy = y + t / 3 - 1;
            int xc = xx + t % 3 - 1;
            bool ok = (yy >= 0 && yy < H && xc >= 0 && xc < W);
            v[t] = ok ? xb[c * HW + yy * W + xc] : 0.f;
        }
#pragma unroll
        for (int t = 0; t < 9; t++) {
            const float4* w4 = (const float4*)&ws[(c * 9 + t) * 20];
            float vv = v[t];
#pragma unroll
            for (int q = 0; q < 5; q++) {
                float4 wq = w4[q];
                acc[q].x += vv * wq.x;
                acc[q].y += vv * wq.y;
                acc[q].z += vv * wq.z;
                acc[q].w += vv * wq.w;
            }
        }
    }

    float a[20];
#pragma unroll
    for (int q = 0; q < 5; q++) {
        a[4*q] = acc[q].x; a[4*q+1] = acc[q].y;
        a[4*q+2] = acc[q].z; a[4*q+3] = acc[q].w;
    }
    float* op = g_off + (long)pid * KK;
#pragma unroll
    for (int kk = 0; kk < 18; kk++) op[kk] = a[kk];
}

// ---------------------------------------------------------------------------
// Kernel 4: fused gather + bf16-split warp-MMA GEMM.
// One block = 128 px (one image row) x 64 outputs, 256 threads (8 warps).
// Gather mapping (coalesced): thread -> (channel quad c4 = (tid&15)*4,
// pixels px = (tid>>4) + 16*i, i=0..7). A warp covers 2 pixels x all 64
// channels per corner load -> ~4 L1 lines per LDG.128 instead of ~32.
// ---------------------------------------------------------------------------
__global__ void __launch_bounds__(256, 2) k_fused(float* __restrict__ out) {
    extern __shared__ char smem[];
    char* sAhi = smem;
    char* sAlo = smem + 18432;
    char* sBhi = smem + 36864;
    char* sBlo = smem + 46080;
    uint32_t sb  = smem_u32(smem);
    uint32_t AHI = sb, ALO = sb + 18432, BHI = sb + 36864, BLO = sb + 46080;

    int tid  = threadIdx.x;
    int lane = tid & 31;
    int wid  = tid >> 5;
    int tile = blockIdx.x;
    int b    = tile >> 7;          // tile = b*128 + y
    int y    = tile & 127;

    // sampler identity: thread -> channel quad + strided pixels
    int c4  = (tid & 15) * 4;
    int pxg = tid >> 4;            // 0..15
    const float* offrow = g_off + (long)(b * HW + y * W) * KK;
    const float* xbase  = g_xt + (long)b * HW * C + c4;

    // mma identity: warp -> m = (wid&3)*32, n = (wid>>2)*32
    int wm = (wid & 3) * 32;
    int wn = (wid >> 2) * 32;
    float acc[2][4][4];
#pragma unroll
    for (int i = 0; i < 2; i++)
#pragma unroll
        for (int j = 0; j < 4; j++)
#pragma unroll
            for (int q = 0; q < 4; q++) acc[i][j][q] = 0.f;

#pragma unroll 1
    for (int k = 0; k < 9; k++) {
        int ky = k / 3 - 1, kx = k % 3 - 1;
        // ---- gather tap k -> A_hi/A_lo (coalesced: 2 px x 64 ch per warp)
#pragma unroll
        for (int i = 0; i < 8; i++) {
            int px = pxg + 16 * i;
            const float* op = offrow + px * KK;
            float py  = op[2*k]     + (float)(y  + ky);
            float pxx = op[2*k + 1] + (float)(px + kx);
            float fy = floorf(py), fx = floorf(pxx);
            float wy = py - fy,    wx = pxx - fx;
            int iy0 = (int)fy, ix0 = (int)fx;
            int iy1 = iy0 + 1, ix1 = ix0 + 1;
            float vy0 = (iy0 >= 0 && iy0 < H) ? 1.f : 0.f;
            float vy1 = (iy1 >= 0 && iy1 < H) ? 1.f : 0.f;
            float vx0 = (ix0 >= 0 && ix0 < W) ? 1.f : 0.f;
            float vx1 = (ix1 >= 0 && ix1 < W) ? 1.f : 0.f;
            float w00 = (1.f - wy) * (1.f - wx) * vy0 * vx0;
            float w01 = (1.f - wy) * wx         * vy0 * vx1;
            float w10 = wy         * (1.f - wx) * vy1 * vx0;
            float w11 = wy         * wx         * vy1 * vx1;
            int cy0 = min(max(iy0, 0), H - 1), cy1 = min(max(iy1, 0), H - 1);
            int cx0 = min(max(ix0, 0), W - 1), cx1 = min(max(ix1, 0), W - 1);
            float4 a00 = *(const float4*)(xbase + (long)(cy0 * W + cx0) * C);
            float4 a01 = *(const float4*)(xbase + (long)(cy0 * W + cx1) * C);
            float4 a10 = *(const float4*)(xbase + (long)(cy1 * W + cx0) * C);
            float4 a11 = *(const float4*)(xbase + (long)(cy1 * W + cx1) * C);
            float s0 = w00*a00.x + w01*a01.x + w10*a10.x + w11*a11.x;
            float s1 = w00*a00.y + w01*a01.y + w10*a10.y + w11*a11.y;
            float s2 = w00*a00.z + w01*a01.z + w10*a10.z + w11*a11.z;
            float s3 = w00*a00.w + w01*a01.w + w10*a10.w + w11*a11.w;
            unsigned h0 = bpack(s0, s1), h1 = bpack(s2, s3);
            float r0 = s0 - __bfloat162float(__float2bfloat16(s0));
            float r1 = s1 - __bfloat162float(__float2bfloat16(s1));
            float r2 = s2 - __bfloat162float(__float2bfloat16(s2));
            float r3 = s3 - __bfloat162float(__float2bfloat16(s3));
            *(uint2*)(sAhi + px * RPAD + c4 * 2) = make_uint2(h0, h1);
            *(uint2*)(sAlo + px * RPAD + c4 * 2) = make_uint2(bpack(r0, r1),
                                                              bpack(r2, r3));
        }
        // ---- load weights tap k -> B_hi/B_lo (padded rows)
        {
            const uint4* bh = (const uint4*)(g_Bhi + k * 4096);
            const uint4* bl = (const uint4*)(g_Blo + k * 4096);
#pragma unroll
            for (int j = 0; j < 2; j++) {
                int idx = tid + j * 256;         // 512 x 16B chunks
                int o   = idx >> 3;
                int kc  = idx & 7;
                *(uint4*)(sBhi + o * RPAD + kc * 16) = bh[idx];
                *(uint4*)(sBlo + o * RPAD + kc * 16) = bl[idx];
            }
        }
        __syncthreads();

        // ---- MMA: 3 passes (hi*hi, hi*lo, lo*hi) x 4 k-steps
#pragma unroll
        for (int p3 = 0; p3 < 3; p3++) {
            uint32_t Ab = (p3 == 2) ? ALO : AHI;
            uint32_t Bb = (p3 == 1) ? BLO : BHI;
#pragma unroll
            for (int ks = 0; ks < 4; ks++) {
                int kcol = ks * 16;
                uint32_t af[2][4], bfr[4][2];
#pragma unroll
                for (int mf = 0; mf < 2; mf++) {
                    uint32_t addr = Ab
                        + (uint32_t)(wm + mf * 16 + (lane & 15)) * RPAD
                        + (uint32_t)(kcol + (lane >> 4) * 8) * 2;
                    ldsm_x4(af[mf], addr);
                }
#pragma unroll
                for (int nf = 0; nf < 4; nf++) {
                    uint32_t addr = Bb
                        + (uint32_t)(wn + nf * 8 + (lane & 7)) * RPAD
                        + (uint32_t)(kcol + ((lane >> 3) & 1) * 8) * 2;
                    ldsm_x2(bfr[nf], addr);
                }
#pragma unroll
                for (int mf = 0; mf < 2; mf++)
#pragma unroll
                    for (int nf = 0; nf < 4; nf++)
                        mma_bf16(acc[mf][nf], af[mf], bfr[nf]);
            }
        }
        __syncthreads();   // done reading A/B before next tap overwrites
    }

    // ---- epilogue: transpose C through smem, store coalesced NCHW rows
    float* Cst = (float*)smem;     // [64 o][132 px]
#pragma unroll
    for (int mf = 0; mf < 2; mf++)
#pragma unroll
        for (int nf = 0; nf < 4; nf++) {
            int row0 = wm + mf * 16 + (lane >> 2);
            int col0 = wn + nf * 8 + (lane & 3) * 2;
            Cst[(col0    ) * 132 + row0    ] = acc[mf][nf][0];
            Cst[(col0 + 1) * 132 + row0    ] = acc[mf][nf][1];
            Cst[(col0    ) * 132 + row0 + 8] = acc[mf][nf][2];
            Cst[(col0 + 1) * 132 + row0 + 8] = acc[mf][nf][3];
        }
    __syncthreads();
    float* ob = out + ((long)b * COUT) * HW + y * W;
#pragma unroll
    for (int j = 0; j < 8; j++) {
        int idx = tid + j * 256;       // 2048 float4 chunks
        int o   = idx >> 5;
        int p4  = (idx & 31) * 4;
        float4 v = *(const float4*)(Cst + o * 132 + p4);
        *(float4*)(ob + (long)o * HW + p4) = v;
    }
}

// ---------------------------------------------------------------------------
extern "C" void kernel_launch(void* const* d_in, const int* in_sizes, int n_in,
                              void* d_out, int out_size) {
    const float* x  = (const float*)d_in[0];
    const float* wp = (const float*)d_in[1];
    const float* bp = (const float*)d_in[2];
    const float* wd = (const float*)d_in[3];
    float* out = (float*)d_out;

    static int smem_set = 0;
    int fused_smem = 55296;
    if (!smem_set) {
        cudaFuncSetAttribute(k_fused, cudaFuncAttributeMaxDynamicSharedMemorySize,
                             fused_smem);
        smem_set = 1;
    }

    k_transpose_x<<<dim3(HW / 32, C / 32, B), dim3(32, 8)>>>(x);
    k_wprep<<<(9 * 64 * 64 + 255) / 256, 256>>>(wd);
    k_offset<<<(B * HW) / 256, 256>>>(x, wp, bp);
    k_fused<<<NTILES, 256, fused_smem>>>(out);
}

// round 9
// speedup vs baseline: 2.3541x; 1.1376x over previous
#include <cuda_runtime.h>
#include <cuda_bf16.h>
#include <math.h>
#include <stdint.h>

#define B    4
#define C    64
#define H    128
#define W    128
#define COUT 64
#define KK   18
#define CK   576
#define HW   16384
#define NTILES 512            // 65536 px / 128; one tile = one image row
#define RPAD 144              // smem row pitch in bytes (72 bf16)

// Scratch (device globals — no runtime allocation allowed)
__device__ float g_xt[B * HW * C];           // x transposed to [b][y][x][c]
__device__ float g_off[B * HW * KK];         // offsets [b][y][x][18]
__device__ __nv_bfloat16 g_Bhi[9 * 64 * 64]; // w_d [tap][o][c] bf16 hi
__device__ __nv_bfloat16 g_Blo[9 * 64 * 64]; // w_d [tap][o][c] bf16 lo
__device__ __nv_bfloat16 g_Phi[9 * 32 * 64]; // w_p [tap][kk(pad32)][c] hi
__device__ __nv_bfloat16 g_Plo[9 * 32 * 64]; // w_p [tap][kk(pad32)][c] lo

// ---------------- warp-MMA helpers (baseline PTX, sm_80+) ----------------
__device__ __forceinline__ uint32_t smem_u32(const void* p) {
    uint32_t a;
    asm("{ .reg .u64 t; cvta.to.shared.u64 t, %1; cvt.u32.u64 %0, t; }"
        : "=r"(a) : "l"(p));
    return a;
}
__device__ __forceinline__ void ldsm_x4(uint32_t* r, uint32_t addr) {
    asm volatile("ldmatrix.sync.aligned.m8n8.x4.shared.b16 {%0,%1,%2,%3}, [%4];"
                 : "=r"(r[0]), "=r"(r[1]), "=r"(r[2]), "=r"(r[3]) : "r"(addr));
}
__device__ __forceinline__ void ldsm_x2(uint32_t* r, uint32_t addr) {
    asm volatile("ldmatrix.sync.aligned.m8n8.x2.shared.b16 {%0,%1}, [%2];"
                 : "=r"(r[0]), "=r"(r[1]) : "r"(addr));
}
__device__ __forceinline__ void mma_bf16(float* c, const uint32_t* a,
                                         const uint32_t* b) {
    asm volatile(
        "mma.sync.aligned.m16n8k16.row.col.f32.bf16.bf16.f32 "
        "{%0,%1,%2,%3}, {%4,%5,%6,%7}, {%8,%9}, {%0,%1,%2,%3};"
        : "+f"(c[0]), "+f"(c[1]), "+f"(c[2]), "+f"(c[3])
        : "r"(a[0]), "r"(a[1]), "r"(a[2]), "r"(a[3]), "r"(b[0]), "r"(b[1]));
}
__device__ __forceinline__ unsigned bpack(float a, float b) {
    __nv_bfloat162 t;
    t.x = __float2bfloat16(a); t.y = __float2bfloat16(b);
    return *reinterpret_cast<unsigned*>(&t);
}

// ---------------------------------------------------------------------------
// Kernel 1: transpose x (B,C,H,W) -> (B,HW,C)
// ---------------------------------------------------------------------------
__global__ void k_transpose_x(const float* __restrict__ x) {
    __shared__ float tile[32][33];
    int b   = blockIdx.z;
    int c0  = blockIdx.y * 32;
    int hw0 = blockIdx.x * 32;
    int tx = threadIdx.x, ty = threadIdx.y;
#pragma unroll
    for (int j = 0; j < 4; j++)
        tile[ty + j * 8][tx] = x[(b * C + c0 + ty + j * 8) * HW + hw0 + tx];
    __syncthreads();
#pragma unroll
    for (int j = 0; j < 4; j++)
        g_xt[(b * HW + hw0 + ty + j * 8) * C + c0 + tx] = tile[tx][ty + j * 8];
}

// ---------------------------------------------------------------------------
// Kernel 2: weight prep — bf16 hi/lo split for both w_d and w_p
// ---------------------------------------------------------------------------
__global__ void k_wprep(const float* __restrict__ wd,
                        const float* __restrict__ wp) {
    int i = blockIdx.x * 256 + threadIdx.x;
    if (i < 9 * 64 * 64) {
        int c = i & 63, o = (i >> 6) & 63, k = i >> 12;
        float v = wd[o * CK + c * 9 + k];
        __nv_bfloat16 h = __float2bfloat16(v);
        g_Bhi[k * 4096 + o * 64 + c] = h;
        g_Blo[k * 4096 + o * 64 + c] = __float2bfloat16(v - __bfloat162float(h));
    } else if (i < 9 * 64 * 64 + 9 * 32 * 64) {
        int j = i - 9 * 64 * 64;
        int c = j & 63, kk = (j >> 6) & 31, k = j >> 11;
        float v = (kk < 18) ? wp[kk * CK + c * 9 + k] : 0.f;
        __nv_bfloat16 h = __float2bfloat16(v);
        g_Phi[k * 2048 + kk * 64 + c] = h;
        g_Plo[k * 2048 + kk * 64 + c] = __float2bfloat16(v - __bfloat162float(h));
    }
}

// ---------------------------------------------------------------------------
// Kernel 3: offset conv as bf16-split HMMA GEMM.
// One block = one image row (128 px) x 18 (pad 32) outputs, 256 threads.
// Per tap (fixed shift): coalesced load 128px x 64ch from g_xt -> A hi/lo;
// weights tap -> B hi/lo; 8 warps: m=(wid&3)*32 (2x16), n=(wid>>2)*16 (2x8).
// ---------------------------------------------------------------------------
__global__ void __launch_bounds__(256) k_off2(const float* __restrict__ bp) {
    extern __shared__ char smem[];
    char* sAhi = smem;
    char* sAlo = smem + 18432;
    char* sBhi = smem + 36864;
    char* sBlo = smem + 41472;
    uint32_t sb  = smem_u32(smem);
    uint32_t AHI = sb, ALO = sb + 18432, BHI = sb + 36864, BLO = sb + 41472;

    int tid  = threadIdx.x;
    int lane = tid & 31;
    int wid  = tid >> 5;
    int tile = blockIdx.x;
    int b    = tile >> 7;
    int y    = tile & 127;

    int c4  = (tid & 15) * 4;
    int pxg = tid >> 4;
    const float* xbase = g_xt + (long)b * HW * C + c4;

    int wm = (wid & 3) * 32;
    int wn = (wid >> 2) * 16;
    float acc[2][2][4];
#pragma unroll
    for (int i = 0; i < 2; i++)
#pragma unroll
        for (int j = 0; j < 2; j++)
#pragma unroll
            for (int q = 0; q < 4; q++) acc[i][j][q] = 0.f;

#pragma unroll 1
    for (int k = 0; k < 9; k++) {
        int ky = k / 3 - 1, kx = k % 3 - 1;
        int yy = y + ky;
        bool yok = (yy >= 0 && yy < H);
        // ---- A: fixed-tap row load (coalesced)
#pragma unroll
        for (int i = 0; i < 8; i++) {
            int px = pxg + 16 * i;
            int xx = px + kx;
            float4 v = make_float4(0.f, 0.f, 0.f, 0.f);
            if (yok && xx >= 0 && xx < W)
                v = *(const float4*)(xbase + (long)(yy * W + xx) * C);
            unsigned h0 = bpack(v.x, v.y), h1 = bpack(v.z, v.w);
            float r0 = v.x - __bfloat162float(__float2bfloat16(v.x));
            float r1 = v.y - __bfloat162float(__float2bfloat16(v.y));
            float r2 = v.z - __bfloat162float(__float2bfloat16(v.z));
            float r3 = v.w - __bfloat162float(__float2bfloat16(v.w));
            *(uint2*)(sAhi + px * RPAD + c4 * 2) = make_uint2(h0, h1);
            *(uint2*)(sAlo + px * RPAD + c4 * 2) = make_uint2(bpack(r0, r1),
                                                              bpack(r2, r3));
        }
        // ---- B: 32x64 bf16 hi+lo (256 uint4 each)
        {
            const uint4* bh = (const uint4*)(g_Phi + k * 2048);
            const uint4* bl = (const uint4*)(g_Plo + k * 2048);
            int o = tid >> 3, kc = tid & 7;
            *(uint4*)(sBhi + o * RPAD + kc * 16) = bh[tid];
            *(uint4*)(sBlo + o * RPAD + kc * 16) = bl[tid];
        }
        __syncthreads();

#pragma unroll
        for (int p3 = 0; p3 < 3; p3++) {
            uint32_t Ab = (p3 == 2) ? ALO : AHI;
            uint32_t Bb = (p3 == 1) ? BLO : BHI;
#pragma unroll
            for (int ks = 0; ks < 4; ks++) {
                int kcol = ks * 16;
                uint32_t af[2][4], bfr[2][2];
#pragma unroll
                for (int mf = 0; mf < 2; mf++) {
                    uint32_t addr = Ab
                        + (uint32_t)(wm + mf * 16 + (lane & 15)) * RPAD
                        + (uint32_t)(kcol + (lane >> 4) * 8) * 2;
                    ldsm_x4(af[mf], addr);
                }
#pragma unroll
                for (int nf = 0; nf < 2; nf++) {
                    uint32_t addr = Bb
                        + (uint32_t)(wn + nf * 8 + (lane & 7)) * RPAD
                        + (uint32_t)(kcol + ((lane >> 3) & 1) * 8) * 2;
                    ldsm_x2(bfr[nf], addr);
                }
#pragma unroll
                for (int mf = 0; mf < 2; mf++)
#pragma unroll
                    for (int nf = 0; nf < 2; nf++)
                        mma_bf16(acc[mf][nf], af[mf], bfr[nf]);
            }
        }
        __syncthreads();
    }

    // ---- epilogue: stage C [128px][pitch 20], add bias, write g_off
    float* Cst = (float*)smem;
#pragma unroll
    for (int mf = 0; mf < 2; mf++)
#pragma unroll
        for (int nf = 0; nf < 2; nf++) {
            int row0 = wm + mf * 16 + (lane >> 2);
            int col0 = wn + nf * 8 + (lane & 3) * 2;
            if (col0 < 18) {
                Cst[(row0    ) * 20 + col0] = acc[mf][nf][0];
                Cst[(row0 + 8) * 20 + col0] = acc[mf][nf][2];
            }
            if (col0 + 1 < 18) {
                Cst[(row0    ) * 20 + col0 + 1] = acc[mf][nf][1];
                Cst[(row0 + 8) * 20 + col0 + 1] = acc[mf][nf][3];
            }
        }
    __syncthreads();
    {
        int px = tid >> 1;
        int g  = tid & 1;
        float* op = g_off + (long)(b * HW + y * W + px) * KK;
#pragma unroll
        for (int j = 0; j < 9; j++) {
            int kk = g * 9 + j;
            op[kk] = Cst[px * 20 + kk] + bp[kk];
        }
    }
}

// ---------------------------------------------------------------------------
// Kernel 4: fused gather + bf16-split warp-MMA GEMM.
// One block = 128 px x 64 outputs, 256 threads (8 warps).
// Phase 0: precompute ALL taps' bilinear weights + corner offsets (smem).
// Per tap: coalesced gather (2 LDS + 4 LDG per px) -> A hi/lo; MMA.
// ---------------------------------------------------------------------------
__global__ void __launch_bounds__(256, 2) k_fused(float* __restrict__ out) {
    extern __shared__ char smem[];
    char* sAhi = smem;
    char* sAlo = smem + 18432;
    char* sBhi = smem + 36864;
    char* sBlo = smem + 46080;
    float4* PW = (float4*)(smem + 55296);   // [9*128] bilinear weights
    int4*   PA = (int4*)(smem + 73728);     // [9*128] corner element offsets
    uint32_t sb  = smem_u32(smem);
    uint32_t AHI = sb, ALO = sb + 18432, BHI = sb + 36864, BLO = sb + 46080;

    int tid  = threadIdx.x;
    int lane = tid & 31;
    int wid  = tid >> 5;
    int tile = blockIdx.x;
    int b    = tile >> 7;
    int y    = tile & 127;

    // ---- Phase 0: per-pixel per-tap bilinear precompute (1152 items)
    {
        const float* offrow = g_off + (long)(b * HW + y * W) * KK;
#pragma unroll
        for (int it = tid; it < 9 * 128; it += 256) {
            int k  = it >> 7;
            int px = it & 127;
            int ky = k / 3 - 1, kx = k % 3 - 1;
            const float* op = offrow + px * KK;
            float py  = op[2*k]     + (float)(y  + ky);
            float pxx = op[2*k + 1] + (float)(px + kx);
            float fy = floorf(py), fx = floorf(pxx);
            float wy = py - fy,    wx = pxx - fx;
            int iy0 = (int)fy, ix0 = (int)fx;
            int iy1 = iy0 + 1, ix1 = ix0 + 1;
            float vy0 = (iy0 >= 0 && iy0 < H) ? 1.f : 0.f;
            float vy1 = (iy1 >= 0 && iy1 < H) ? 1.f : 0.f;
            float vx0 = (ix0 >= 0 && ix0 < W) ? 1.f : 0.f;
            float vx1 = (ix1 >= 0 && ix1 < W) ? 1.f : 0.f;
            PW[it] = make_float4((1.f - wy) * (1.f - wx) * vy0 * vx0,
                                 (1.f - wy) * wx         * vy0 * vx1,
                                 wy         * (1.f - wx) * vy1 * vx0,
                                 wy         * wx         * vy1 * vx1);
            int cy0 = min(max(iy0, 0), H - 1), cy1 = min(max(iy1, 0), H - 1);
            int cx0 = min(max(ix0, 0), W - 1), cx1 = min(max(ix1, 0), W - 1);
            PA[it] = make_int4((cy0 * W + cx0) * C, (cy0 * W + cx1) * C,
                               (cy1 * W + cx0) * C, (cy1 * W + cx1) * C);
        }
    }
    __syncthreads();

    int c4  = (tid & 15) * 4;
    int pxg = tid >> 4;
    const float* xbase = g_xt + (long)b * HW * C + c4;

    int wm = (wid & 3) * 32;
    int wn = (wid >> 2) * 32;
    float acc[2][4][4];
#pragma unroll
    for (int i = 0; i < 2; i++)
#pragma unroll
        for (int j = 0; j < 4; j++)
#pragma unroll
            for (int q = 0; q < 4; q++) acc[i][j][q] = 0.f;

#pragma unroll 1
    for (int k = 0; k < 9; k++) {
        // ---- gather tap k using precomputed weights/addresses
#pragma unroll
        for (int i = 0; i < 8; i++) {
            int px = pxg + 16 * i;
            float4 wt = PW[k * 128 + px];
            int4   ad = PA[k * 128 + px];
            float4 a00 = *(const float4*)(xbase + ad.x);
            float4 a01 = *(const float4*)(xbase + ad.y);
            float4 a10 = *(const float4*)(xbase + ad.z);
            float4 a11 = *(const float4*)(xbase + ad.w);
            float s0 = wt.x*a00.x + wt.y*a01.x + wt.z*a10.x + wt.w*a11.x;
            float s1 = wt.x*a00.y + wt.y*a01.y + wt.z*a10.y + wt.w*a11.y;
            float s2 = wt.x*a00.z + wt.y*a01.z + wt.z*a10.z + wt.w*a11.z;
            float s3 = wt.x*a00.w + wt.y*a01.w + wt.z*a10.w + wt.w*a11.w;
            unsigned h0 = bpack(s0, s1), h1 = bpack(s2, s3);
            float r0 = s0 - __bfloat162float(__float2bfloat16(s0));
            float r1 = s1 - __bfloat162float(__float2bfloat16(s1));
            float r2 = s2 - __bfloat162float(__float2bfloat16(s2));
            float r3 = s3 - __bfloat162float(__float2bfloat16(s3));
            *(uint2*)(sAhi + px * RPAD + c4 * 2) = make_uint2(h0, h1);
            *(uint2*)(sAlo + px * RPAD + c4 * 2) = make_uint2(bpack(r0, r1),
                                                              bpack(r2, r3));
        }
        // ---- weights tap k -> B hi/lo
        {
            const uint4* bh = (const uint4*)(g_Bhi + k * 4096);
            const uint4* bl = (const uint4*)(g_Blo + k * 4096);
#pragma unroll
            for (int j = 0; j < 2; j++) {
                int idx = tid + j * 256;
                int o   = idx >> 3;
                int kc  = idx & 7;
                *(uint4*)(sBhi + o * RPAD + kc * 16) = bh[idx];
                *(uint4*)(sBlo + o * RPAD + kc * 16) = bl[idx];
            }
        }
        __syncthreads();

        // ---- MMA: 3 passes (hi*hi, hi*lo, lo*hi) x 4 k-steps
#pragma unroll
        for (int p3 = 0; p3 < 3; p3++) {
            uint32_t Ab = (p3 == 2) ? ALO : AHI;
            uint32_t Bb = (p3 == 1) ? BLO : BHI;
#pragma unroll
            for (int ks = 0; ks < 4; ks++) {
                int kcol = ks * 16;
                uint32_t af[2][4], bfr[4][2];
#pragma unroll
                for (int mf = 0; mf < 2; mf++) {
                    uint32_t addr = Ab
                        + (uint32_t)(wm + mf * 16 + (lane & 15)) * RPAD
                        + (uint32_t)(kcol + (lane >> 4) * 8) * 2;
                    ldsm_x4(af[mf], addr);
                }
#pragma unroll
                for (int nf = 0; nf < 4; nf++) {
                    uint32_t addr = Bb
                        + (uint32_t)(wn + nf * 8 + (lane & 7)) * RPAD
                        + (uint32_t)(kcol + ((lane >> 3) & 1) * 8) * 2;
                    ldsm_x2(bfr[nf], addr);
                }
#pragma unroll
                for (int mf = 0; mf < 2; mf++)
#pragma unroll
                    for (int nf = 0; nf < 4; nf++)
                        mma_bf16(acc[mf][nf], af[mf], bfr[nf]);
            }
        }
        __syncthreads();
    }

    // ---- epilogue: transpose C through smem, store coalesced NCHW rows
    float* Cst = (float*)smem;     // [64 o][132 px]
#pragma unroll
    for (int mf = 0; mf < 2; mf++)
#pragma unroll
        for (int nf = 0; nf < 4; nf++) {
            int row0 = wm + mf * 16 + (lane >> 2);
            int col0 = wn + nf * 8 + (lane & 3) * 2;
            Cst[(col0    ) * 132 + row0    ] = acc[mf][nf][0];
            Cst[(col0 + 1) * 132 + row0    ] = acc[mf][nf][1];
            Cst[(col0    ) * 132 + row0 + 8] = acc[mf][nf][2];
            Cst[(col0 + 1) * 132 + row0 + 8] = acc[mf][nf][3];
        }
    __syncthreads();
    float* ob = out + ((long)b * COUT) * HW + y * W;
#pragma unroll
    for (int j = 0; j < 8; j++) {
        int idx = tid + j * 256;
        int o   = idx >> 5;
        int p4  = (idx & 31) * 4;
        float4 v = *(const float4*)(Cst + o * 132 + p4);
        *(float4*)(ob + (long)o * HW + p4) = v;
    }
}

// ---------------------------------------------------------------------------
extern "C" void kernel_launch(void* const* d_in, const int* in_sizes, int n_in,
                              void* d_out, int out_size) {
    const float* x  = (const float*)d_in[0];
    const float* wp = (const float*)d_in[1];
    const float* bp = (const float*)d_in[2];
    const float* wd = (const float*)d_in[3];
    float* out = (float*)d_out;

    static int smem_set = 0;
    int fused_smem = 92160;   // A/B tiles + 36 KB precompute
    int off2_smem  = 46080;
    if (!smem_set) {
        cudaFuncSetAttribute(k_fused, cudaFuncAttributeMaxDynamicSharedMemorySize,
                             fused_smem);
        cudaFuncSetAttribute(k_off2, cudaFuncAttributeMaxDynamicSharedMemorySize,
                             off2_smem);
        smem_set = 1;
    }

    k_transpose_x<<<dim3(HW / 32, C / 32, B), dim3(32, 8)>>>(x);
    k_wprep<<<(9 * 64 * 64 + 9 * 32 * 64 + 255) / 256, 256>>>(wd, wp);
    k_off2<<<NTILES, 256, off2_smem>>>(bp);
    k_fused<<<NTILES, 256, fused_smem>>>(out);
}

// round 10
// speedup vs baseline: 2.5480x; 1.0824x over previous
#include <cuda_runtime.h>
#include <cuda_bf16.h>
#include <math.h>
#include <stdint.h>

#define B    4
#define C    64
#define H    128
#define W    128
#define COUT 64
#define KK   18
#define CK   576
#define HW   16384
#define NTILES 512            // 65536 px / 128; one tile = one image row
#define RPAD 144              // smem row pitch in bytes (72 bf16)

// Scratch (device globals — no runtime allocation allowed)
__device__ float g_xt[B * HW * C];           // x transposed to [b][y][x][c]
__device__ float g_off[B * HW * KK];         // offsets [b][y][x][18]
__device__ __nv_bfloat16 g_Bhi[9 * 64 * 64]; // w_d [tap][o][c] bf16 hi
__device__ __nv_bfloat16 g_Blo[9 * 64 * 64]; // w_d [tap][o][c] bf16 lo
__device__ __nv_bfloat16 g_Phi[9 * 32 * 64]; // w_p [tap][kk(pad32)][c] hi
__device__ __nv_bfloat16 g_Plo[9 * 32 * 64]; // w_p [tap][kk(pad32)][c] lo

// ---------------- warp-MMA helpers (baseline PTX, sm_80+) ----------------
__device__ __forceinline__ uint32_t smem_u32(const void* p) {
    uint32_t a;
    asm("{ .reg .u64 t; cvta.to.shared.u64 t, %1; cvt.u32.u64 %0, t; }"
        : "=r"(a) : "l"(p));
    return a;
}
__device__ __forceinline__ void ldsm_x4(uint32_t* r, uint32_t addr) {
    asm volatile("ldmatrix.sync.aligned.m8n8.x4.shared.b16 {%0,%1,%2,%3}, [%4];"
                 : "=r"(r[0]), "=r"(r[1]), "=r"(r[2]), "=r"(r[3]) : "r"(addr));
}
__device__ __forceinline__ void ldsm_x2(uint32_t* r, uint32_t addr) {
    asm volatile("ldmatrix.sync.aligned.m8n8.x2.shared.b16 {%0,%1}, [%2];"
                 : "=r"(r[0]), "=r"(r[1]) : "r"(addr));
}
__device__ __forceinline__ void mma_bf16(float* c, const uint32_t* a,
                                         const uint32_t* b) {
    asm volatile(
        "mma.sync.aligned.m16n8k16.row.col.f32.bf16.bf16.f32 "
        "{%0,%1,%2,%3}, {%4,%5,%6,%7}, {%8,%9}, {%0,%1,%2,%3};"
        : "+f"(c[0]), "+f"(c[1]), "+f"(c[2]), "+f"(c[3])
        : "r"(a[0]), "r"(a[1]), "r"(a[2]), "r"(a[3]), "r"(b[0]), "r"(b[1]));
}
__device__ __forceinline__ unsigned bpack(float a, float b) {
    __nv_bfloat162 t;
    t.x = __float2bfloat16(a); t.y = __float2bfloat16(b);
    return *reinterpret_cast<unsigned*>(&t);
}

// ---------------------------------------------------------------------------
// Kernel 1: transpose x (B,C,H,W) -> (B,HW,C)
// ---------------------------------------------------------------------------
__global__ void k_transpose_x(const float* __restrict__ x) {
    __shared__ float tile[32][33];
    int b   = blockIdx.z;
    int c0  = blockIdx.y * 32;
    int hw0 = blockIdx.x * 32;
    int tx = threadIdx.x, ty = threadIdx.y;
#pragma unroll
    for (int j = 0; j < 4; j++)
        tile[ty + j * 8][tx] = x[(b * C + c0 + ty + j * 8) * HW + hw0 + tx];
    __syncthreads();
#pragma unroll
    for (int j = 0; j < 4; j++)
        g_xt[(b * HW + hw0 + ty + j * 8) * C + c0 + tx] = tile[tx][ty + j * 8];
}

// ---------------------------------------------------------------------------
// Kernel 2: weight prep — bf16 hi/lo split for both w_d and w_p
// ---------------------------------------------------------------------------
__global__ void k_wprep(const float* __restrict__ wd,
                        const float* __restrict__ wp) {
    int i = blockIdx.x * 256 + threadIdx.x;
    if (i < 9 * 64 * 64) {
        int c = i & 63, o = (i >> 6) & 63, k = i >> 12;
        float v = wd[o * CK + c * 9 + k];
        __nv_bfloat16 h = __float2bfloat16(v);
        g_Bhi[k * 4096 + o * 64 + c] = h;
        g_Blo[k * 4096 + o * 64 + c] = __float2bfloat16(v - __bfloat162float(h));
    } else if (i < 9 * 64 * 64 + 9 * 32 * 64) {
        int j = i - 9 * 64 * 64;
        int c = j & 63, kk = (j >> 6) & 31, k = j >> 11;
        float v = (kk < 18) ? wp[kk * CK + c * 9 + k] : 0.f;
        __nv_bfloat16 h = __float2bfloat16(v);
        g_Phi[k * 2048 + kk * 64 + c] = h;
        g_Plo[k * 2048 + kk * 64 + c] = __float2bfloat16(v - __bfloat162float(h));
    }
}

// ---------------------------------------------------------------------------
// Kernel 3: offset conv as bf16-split HMMA GEMM.
// One block = one image row (128 px) x 18 (pad 32) outputs, 256 threads.
// ---------------------------------------------------------------------------
__global__ void __launch_bounds__(256) k_off2(const float* __restrict__ bp) {
    extern __shared__ char smem[];
    char* sAhi = smem;
    char* sAlo = smem + 18432;
    char* sBhi = smem + 36864;
    char* sBlo = smem + 41472;
    uint32_t sb  = smem_u32(smem);
    uint32_t AHI = sb, ALO = sb + 18432, BHI = sb + 36864, BLO = sb + 41472;

    int tid  = threadIdx.x;
    int lane = tid & 31;
    int wid  = tid >> 5;
    int tile = blockIdx.x;
    int b    = tile >> 7;
    int y    = tile & 127;

    int c4  = (tid & 15) * 4;
    int pxg = tid >> 4;
    const float* xbase = g_xt + (long)b * HW * C + c4;

    int wm = (wid & 3) * 32;
    int wn = (wid >> 2) * 16;
    float acc[2][2][4];
#pragma unroll
    for (int i = 0; i < 2; i++)
#pragma unroll
        for (int j = 0; j < 2; j++)
#pragma unroll
            for (int q = 0; q < 4; q++) acc[i][j][q] = 0.f;

#pragma unroll 1
    for (int k = 0; k < 9; k++) {
        int ky = k / 3 - 1, kx = k % 3 - 1;
        int yy = y + ky;
        bool yok = (yy >= 0 && yy < H);
#pragma unroll
        for (int i = 0; i < 8; i++) {
            int px = pxg + 16 * i;
            int xx = px + kx;
            float4 v = make_float4(0.f, 0.f, 0.f, 0.f);
            if (yok && xx >= 0 && xx < W)
                v = *(const float4*)(xbase + (long)(yy * W + xx) * C);
            unsigned h0 = bpack(v.x, v.y), h1 = bpack(v.z, v.w);
            float r0 = v.x - __bfloat162float(__float2bfloat16(v.x));
            float r1 = v.y - __bfloat162float(__float2bfloat16(v.y));
            float r2 = v.z - __bfloat162float(__float2bfloat16(v.z));
            float r3 = v.w - __bfloat162float(__float2bfloat16(v.w));
            *(uint2*)(sAhi + px * RPAD + c4 * 2) = make_uint2(h0, h1);
            *(uint2*)(sAlo + px * RPAD + c4 * 2) = make_uint2(bpack(r0, r1),
                                                              bpack(r2, r3));
        }
        {
            const uint4* bh = (const uint4*)(g_Phi + k * 2048);
            const uint4* bl = (const uint4*)(g_Plo + k * 2048);
            int o = tid >> 3, kc = tid & 7;
            *(uint4*)(sBhi + o * RPAD + kc * 16) = bh[tid];
            *(uint4*)(sBlo + o * RPAD + kc * 16) = bl[tid];
        }
        __syncthreads();

#pragma unroll
        for (int ks = 0; ks < 4; ks++) {
            int kcol = ks * 16;
            uint32_t ahi[2][4], alo[2][4], bhi[2][2], blo[2][2];
#pragma unroll
            for (int mf = 0; mf < 2; mf++) {
                uint32_t ar = (uint32_t)(wm + mf * 16 + (lane & 15)) * RPAD
                            + (uint32_t)(kcol + (lane >> 4) * 8) * 2;
                ldsm_x4(ahi[mf], AHI + ar);
                ldsm_x4(alo[mf], ALO + ar);
            }
#pragma unroll
            for (int nf = 0; nf < 2; nf++) {
                uint32_t br = (uint32_t)(wn + nf * 8 + (lane & 7)) * RPAD
                            + (uint32_t)(kcol + ((lane >> 3) & 1) * 8) * 2;
                ldsm_x2(bhi[nf], BHI + br);
                ldsm_x2(blo[nf], BLO + br);
            }
#pragma unroll
            for (int mf = 0; mf < 2; mf++)
#pragma unroll
                for (int nf = 0; nf < 2; nf++) {
                    mma_bf16(acc[mf][nf], ahi[mf], bhi[nf]);
                    mma_bf16(acc[mf][nf], ahi[mf], blo[nf]);
                    mma_bf16(acc[mf][nf], alo[mf], bhi[nf]);
                }
        }
        __syncthreads();
    }

    float* Cst = (float*)smem;
#pragma unroll
    for (int mf = 0; mf < 2; mf++)
#pragma unroll
        for (int nf = 0; nf < 2; nf++) {
            int row0 = wm + mf * 16 + (lane >> 2);
            int col0 = wn + nf * 8 + (lane & 3) * 2;
            if (col0 < 18) {
                Cst[(row0    ) * 20 + col0] = acc[mf][nf][0];
                Cst[(row0 + 8) * 20 + col0] = acc[mf][nf][2];
            }
            if (col0 + 1 < 18) {
                Cst[(row0    ) * 20 + col0 + 1] = acc[mf][nf][1];
                Cst[(row0 + 8) * 20 + col0 + 1] = acc[mf][nf][3];
            }
        }
    __syncthreads();
    {
        int px = tid >> 1;
        int g  = tid & 1;
        float* op = g_off + (long)(b * HW + y * W + px) * KK;
#pragma unroll
        for (int j = 0; j < 9; j++) {
            int kk = g * 9 + j;
            op[kk] = Cst[px * 20 + kk] + bp[kk];
        }
    }
}

// ---------------------------------------------------------------------------
// Kernel 4: fused gather + bf16-split warp-MMA GEMM (R8 gather + fused-pass
// MMA: A/B hi+lo fragments loaded once per k-step, 3 passes from registers).
// ---------------------------------------------------------------------------
__global__ void __launch_bounds__(256, 2) k_fused(float* __restrict__ out) {
    extern __shared__ char smem[];
    char* sAhi = smem;
    char* sAlo = smem + 18432;
    char* sBhi = smem + 36864;
    char* sBlo = smem + 46080;
    uint32_t sb  = smem_u32(smem);
    uint32_t AHI = sb, ALO = sb + 18432, BHI = sb + 36864, BLO = sb + 46080;

    int tid  = threadIdx.x;
    int lane = tid & 31;
    int wid  = tid >> 5;
    int tile = blockIdx.x;
    int b    = tile >> 7;
    int y    = tile & 127;

    // sampler identity: thread -> channel quad + strided pixels
    int c4  = (tid & 15) * 4;
    int pxg = tid >> 4;
    const float* offrow = g_off + (long)(b * HW + y * W) * KK;
    const float* xbase  = g_xt + (long)b * HW * C + c4;

    int wm = (wid & 3) * 32;
    int wn = (wid >> 2) * 32;
    float acc[2][4][4];
#pragma unroll
    for (int i = 0; i < 2; i++)
#pragma unroll
        for (int j = 0; j < 4; j++)
#pragma unroll
            for (int q = 0; q < 4; q++) acc[i][j][q] = 0.f;

#pragma unroll 1
    for (int k = 0; k < 9; k++) {
        int ky = k / 3 - 1, kx = k % 3 - 1;
        // ---- gather tap k -> A_hi/A_lo (coalesced: 2 px x 64 ch per warp)
#pragma unroll
        for (int i = 0; i < 8; i++) {
            int px = pxg + 16 * i;
            const float* op = offrow + px * KK;
            float py  = op[2*k]     + (float)(y  + ky);
            float pxx = op[2*k + 1] + (float)(px + kx);
            float fy = floorf(py), fx = floorf(pxx);
            float wy = py - fy,    wx = pxx - fx;
            int iy0 = (int)fy, ix0 = (int)fx;
            int iy1 = iy0 + 1, ix1 = ix0 + 1;
            float vy0 = (iy0 >= 0 && iy0 < H) ? 1.f : 0.f;
            float vy1 = (iy1 >= 0 && iy1 < H) ? 1.f : 0.f;
            float vx0 = (ix0 >= 0 && ix0 < W) ? 1.f : 0.f;
            float vx1 = (ix1 >= 0 && ix1 < W) ? 1.f : 0.f;
            float w00 = (1.f - wy) * (1.f - wx) * vy0 * vx0;
            float w01 = (1.f - wy) * wx         * vy0 * vx1;
            float w10 = wy         * (1.f - wx) * vy1 * vx0;
            float w11 = wy         * wx         * vy1 * vx1;
            int cy0 = min(max(iy0, 0), H - 1), cy1 = min(max(iy1, 0), H - 1);
            int cx0 = min(max(ix0, 0), W - 1), cx1 = min(max(ix1, 0), W - 1);
            float4 a00 = *(const float4*)(xbase + (long)(cy0 * W + cx0) * C);
            float4 a01 = *(const float4*)(xbase + (long)(cy0 * W + cx1) * C);
            float4 a10 = *(const float4*)(xbase + (long)(cy1 * W + cx0) * C);
            float4 a11 = *(const float4*)(xbase + (long)(cy1 * W + cx1) * C);
            float s0 = w00*a00.x + w01*a01.x + w10*a10.x + w11*a11.x;
            float s1 = w00*a00.y + w01*a01.y + w10*a10.y + w11*a11.y;
            float s2 = w00*a00.z + w01*a01.z + w10*a10.z + w11*a11.z;
            float s3 = w00*a00.w + w01*a01.w + w10*a10.w + w11*a11.w;
            unsigned h0 = bpack(s0, s1), h1 = bpack(s2, s3);
            float r0 = s0 - __bfloat162float(__float2bfloat16(s0));
            float r1 = s1 - __bfloat162float(__float2bfloat16(s1));
            float r2 = s2 - __bfloat162float(__float2bfloat16(s2));
            float r3 = s3 - __bfloat162float(__float2bfloat16(s3));
            *(uint2*)(sAhi + px * RPAD + c4 * 2) = make_uint2(h0, h1);
            *(uint2*)(sAlo + px * RPAD + c4 * 2) = make_uint2(bpack(r0, r1),
                                                              bpack(r2, r3));
        }
        // ---- weights tap k -> B hi/lo
        {
            const uint4* bh = (const uint4*)(g_Bhi + k * 4096);
            const uint4* bl = (const uint4*)(g_Blo + k * 4096);
#pragma unroll
            for (int j = 0; j < 2; j++) {
                int idx = tid + j * 256;
                int o   = idx >> 3;
                int kc  = idx & 7;
                *(uint4*)(sBhi + o * RPAD + kc * 16) = bh[idx];
                *(uint4*)(sBlo + o * RPAD + kc * 16) = bl[idx];
            }
        }
        __syncthreads();

        // ---- MMA: per k-step, load A/B hi+lo frags once, 3 passes from regs
#pragma unroll
        for (int ks = 0; ks < 4; ks++) {
            int kcol = ks * 16;
            uint32_t ahi[2][4], alo[2][4], bhi[4][2], blo[4][2];
#pragma unroll
            for (int mf = 0; mf < 2; mf++) {
                uint32_t ar = (uint32_t)(wm + mf * 16 + (lane & 15)) * RPAD
                            + (uint32_t)(kcol + (lane >> 4) * 8) * 2;
                ldsm_x4(ahi[mf], AHI + ar);
                ldsm_x4(alo[mf], ALO + ar);
            }
#pragma unroll
            for (int nf = 0; nf < 4; nf++) {
                uint32_t br = (uint32_t)(wn + nf * 8 + (lane & 7)) * RPAD
                            + (uint32_t)(kcol + ((lane >> 3) & 1) * 8) * 2;
                ldsm_x2(bhi[nf], BHI + br);
                ldsm_x2(blo[nf], BLO + br);
            }
#pragma unroll
            for (int mf = 0; mf < 2; mf++)
#pragma unroll
                for (int nf = 0; nf < 4; nf++) {
                    mma_bf16(acc[mf][nf], ahi[mf], bhi[nf]);
                    mma_bf16(acc[mf][nf], ahi[mf], blo[nf]);
                    mma_bf16(acc[mf][nf], alo[mf], bhi[nf]);
                }
        }
        __syncthreads();
    }

    // ---- epilogue: transpose C through smem, store coalesced NCHW rows
    float* Cst = (float*)smem;     // [64 o][132 px]
#pragma unroll
    for (int mf = 0; mf < 2; mf++)
#pragma unroll
        for (int nf = 0; nf < 4; nf++) {
            int row0 = wm + mf * 16 + (lane >> 2);
            int col0 = wn + nf * 8 + (lane & 3) * 2;
            Cst[(col0    ) * 132 + row0    ] = acc[mf][nf][0];
            Cst[(col0 + 1) * 132 + row0    ] = acc[mf][nf][1];
            Cst[(col0    ) * 132 + row0 + 8] = acc[mf][nf][2];
            Cst[(col0 + 1) * 132 + row0 + 8] = acc[mf][nf][3];
        }
    __syncthreads();
    float* ob = out + ((long)b * COUT) * HW + y * W;
#pragma unroll
    for (int j = 0; j < 8; j++) {
        int idx = tid + j * 256;
        int o   = idx >> 5;
        int p4  = (idx & 31) * 4;
        float4 v = *(const float4*)(Cst + o * 132 + p4);
        *(float4*)(ob + (long)o * HW + p4) = v;
    }
}

// ---------------------------------------------------------------------------
extern "C" void kernel_launch(void* const* d_in, const int* in_sizes, int n_in,
                              void* d_out, int out_size) {
    const float* x  = (const float*)d_in[0];
    const float* wp = (const float*)d_in[1];
    const float* bp = (const float*)d_in[2];
    const float* wd = (const float*)d_in[3];
    float* out = (float*)d_out;

    static int smem_set = 0;
    int fused_smem = 55296;
    int off2_smem  = 46080;
    if (!smem_set) {
        cudaFuncSetAttribute(k_fused, cudaFuncAttributeMaxDynamicSharedMemorySize,
                             fused_smem);
        cudaFuncSetAttribute(k_off2, cudaFuncAttributeMaxDynamicSharedMemorySize,
                             off2_smem);
        smem_set = 1;
    }

    k_transpose_x<<<dim3(HW / 32, C / 32, B), dim3(32, 8)>>>(x);
    k_wprep<<<(9 * 64 * 64 + 9 * 32 * 64 + 255) / 256, 256>>>(wd, wp);
    k_off2<<<NTILES, 256, off2_smem>>>(bp);
    k_fused<<<NTILES, 256, fused_smem>>>(out);
}